// round 15
// baseline (speedup 1.0000x reference)
#include <cuda_runtime.h>
#include <math.h>

#define BB 8
#define NN 8192
#define DXc 2
#define EE 128
#define HH 8
#define HDc 16
#define KHc 32
#define FFc 128
#define G1 32
#define G2 32
#define PP 32
#define MM (G1*G2)      // 1024
#define TT (BB*MM)      // 8192
#define TB 8            // tokens per block (one warp per token)

// ---------------- device scratch ----------------
__device__ float g_min[2];
__device__ float g_max[2];
__device__ int   g_count[TT];
__device__ int   g_ptid[TT*PP];
__device__ float g_Alg[HH*EE];
__device__ float2 g_SC[HH];
__device__ float g_lnk[EE];
__device__ float g_dots0[HH];
__device__ float2 g_stats[BB*NN];
__device__ float g_plog[BB*NN*HH];
__device__ float4 g_pWv4[EE/4*EE];   // [r4][f] = (W[4r4][f],W[4r4+1][f],W[4r4+2][f],W[4r4+3][f])
__device__ float4 g_pWo4[EE/4*EE];
__device__ float4 g_pW14[EE/4*FFc];
__device__ float4 g_pW24[FFc/4*EE];

// ---------------- helpers ----------------
__device__ __forceinline__ void atomicMinF(float* addr, float v){
  if (v >= 0.f) atomicMin((int*)addr, __float_as_int(v));
  else          atomicMax((unsigned int*)addr, __float_as_uint(v));
}
__device__ __forceinline__ void atomicMaxF(float* addr, float v){
  if (v >= 0.f) atomicMax((int*)addr, __float_as_int(v));
  else          atomicMin((unsigned int*)addr, __float_as_uint(v));
}
__device__ __forceinline__ void fma2(unsigned long long &d, unsigned long long a, unsigned long long b){
  asm("fma.rn.f32x2 %0, %1, %2, %0;" : "+l"(d) : "l"(a), "l"(b));
}
__device__ __forceinline__ float unpack_sum(unsigned long long v){
  float lo, hi;
  asm("mov.b64 {%0,%1}, %2;" : "=f"(lo), "=f"(hi) : "l"(v));
  return lo + hi;
}
// lane-specialized reduce (sum) of 8 values
__device__ __forceinline__ float reduce8(const float* v, int lane){
  float sh[8];
  #pragma unroll
  for (int i=0;i<8;i++) sh[i] = __shfl_xor_sync(0xffffffffu, v[i], 16);
  float a[4];
  bool hi4 = (lane & 16) != 0;
  #pragma unroll
  for (int i=0;i<4;i++) a[i] = hi4 ? (v[i+4]+sh[i+4]) : (v[i]+sh[i]);
  float bsh[4];
  #pragma unroll
  for (int i=0;i<4;i++) bsh[i] = __shfl_xor_sync(0xffffffffu, a[i], 8);
  float b[2];
  bool hi2 = (lane & 8) != 0;
  #pragma unroll
  for (int i=0;i<2;i++) b[i] = hi2 ? (a[i+2]+bsh[i+2]) : (a[i]+bsh[i]);
  float c0 = __shfl_xor_sync(0xffffffffu, b[0], 4);
  float c1 = __shfl_xor_sync(0xffffffffu, b[1], 4);
  float c = (lane & 4) ? (b[1]+c1) : (b[0]+c0);
  c += __shfl_xor_sync(0xffffffffu, c, 2);
  c += __shfl_xor_sync(0xffffffffu, c, 1);
  return c;
}
// same, but max
__device__ __forceinline__ float reduce8_max(const float* v, int lane){
  float sh[8];
  #pragma unroll
  for (int i=0;i<8;i++) sh[i] = __shfl_xor_sync(0xffffffffu, v[i], 16);
  float a[4];
  bool hi4 = (lane & 16) != 0;
  #pragma unroll
  for (int i=0;i<4;i++) a[i] = hi4 ? fmaxf(v[i+4],sh[i+4]) : fmaxf(v[i],sh[i]);
  float bsh[4];
  #pragma unroll
  for (int i=0;i<4;i++) bsh[i] = __shfl_xor_sync(0xffffffffu, a[i], 8);
  float b[2];
  bool hi2 = (lane & 8) != 0;
  #pragma unroll
  for (int i=0;i<2;i++) b[i] = hi2 ? fmaxf(a[i+2],bsh[i+2]) : fmaxf(a[i],bsh[i]);
  float c0 = __shfl_xor_sync(0xffffffffu, b[0], 4);
  float c1 = __shfl_xor_sync(0xffffffffu, b[1], 4);
  float c = (lane & 4) ? fmaxf(b[1],c1) : fmaxf(b[0],c0);
  c = fmaxf(c, __shfl_xor_sync(0xffffffffu, c, 2));
  c = fmaxf(c, __shfl_xor_sync(0xffffffffu, c, 1));
  return c;
}

// ---------------- kernel 0: init + pack weights (float4 e-quads) ----------------
__global__ void k_pre(const float* __restrict__ Wv, const float* __restrict__ Wo,
                      const float* __restrict__ fW1, const float* __restrict__ fW2){
  int i = blockIdx.x*blockDim.x + threadIdx.x;   // 0..8191
  g_count[i] = 0;
  if (i < 2){
    g_min[i] = __int_as_float(0x7f800000);
    g_max[i] = __int_as_float(0xff800000);
  }
  if (i < EE/4*EE){
    int r4 = i >> 7, f = i & 127;
    int e0 = 4*r4;
    g_pWv4[i] = make_float4(Wv[e0*EE+f],  Wv[(e0+1)*EE+f],  Wv[(e0+2)*EE+f],  Wv[(e0+3)*EE+f]);
    g_pWo4[i] = make_float4(Wo[e0*EE+f],  Wo[(e0+1)*EE+f],  Wo[(e0+2)*EE+f],  Wo[(e0+3)*EE+f]);
    g_pW14[i] = make_float4(fW1[e0*FFc+f],fW1[(e0+1)*FFc+f],fW1[(e0+2)*FFc+f],fW1[(e0+3)*FFc+f]);
    g_pW24[i] = make_float4(fW2[e0*EE+f], fW2[(e0+1)*EE+f], fW2[(e0+2)*EE+f], fW2[(e0+3)*EE+f]);
  }
}

// ---------------- kernel 1: global min/max ----------------
__global__ void k_minmax(const float* __restrict__ x){
  float mn0=1e38f, mn1=1e38f, mx0=-1e38f, mx1=-1e38f;
  const float4* x4 = (const float4*)x;
  for (int i = blockIdx.x*blockDim.x + threadIdx.x; i < BB*NN/2; i += gridDim.x*blockDim.x){
    float4 v = x4[i];
    mn0 = fminf(mn0, fminf(v.x, v.z)); mx0 = fmaxf(mx0, fmaxf(v.x, v.z));
    mn1 = fminf(mn1, fminf(v.y, v.w)); mx1 = fmaxf(mx1, fmaxf(v.y, v.w));
  }
  #pragma unroll
  for (int o=16;o;o>>=1){
    mn0 = fminf(mn0, __shfl_xor_sync(0xffffffffu, mn0, o));
    mx0 = fmaxf(mx0, __shfl_xor_sync(0xffffffffu, mx0, o));
    mn1 = fminf(mn1, __shfl_xor_sync(0xffffffffu, mn1, o));
    mx1 = fmaxf(mx1, __shfl_xor_sync(0xffffffffu, mx1, o));
  }
  __shared__ float s[4][8];
  int w = threadIdx.x>>5, l = threadIdx.x&31;
  if (l==0){ s[0][w]=mn0; s[1][w]=mx0; s[2][w]=mn1; s[3][w]=mx1; }
  __syncthreads();
  if (threadIdx.x==0){
    int nw = blockDim.x>>5;
    float a=s[0][0], b=s[1][0], c=s[2][0], d=s[3][0];
    for (int j=1;j<nw;j++){ a=fminf(a,s[0][j]); b=fmaxf(b,s[1][j]); c=fminf(c,s[2][j]); d=fmaxf(d,s[3][j]); }
    atomicMinF(&g_min[0], a); atomicMaxF(&g_max[0], b);
    atomicMinF(&g_min[1], c); atomicMaxF(&g_max[1], d);
  }
}

// ---------------- kernel 2: precompute (8 blocks, block = head) ----------------
__global__ void __launch_bounds__(1024) k_prep(
    const float* __restrict__ latent,
    const float* __restrict__ Wq, const float* __restrict__ Wk,
    const float* __restrict__ lnq_g, const float* __restrict__ lnq_b,
    const float* __restrict__ lnk_g, const float* __restrict__ lnk_b,
    const float* __restrict__ kb1, const float* __restrict__ kW2,
    const float* __restrict__ kb2){
  __shared__ float s_lnq[EE], s_lnk[EE], s_q[EE];
  __shared__ float s_part[8][EE];
  __shared__ float s_red[8];
  __shared__ float s_r3[4][3];
  __shared__ float s_kbv;
  int tid = threadIdx.x, lane = tid & 31, w = tid >> 5;
  int h = blockIdx.x;

  float v = (tid < EE) ? latent[tid] : 0.f;
  float sv = v;
  #pragma unroll
  for (int o=16;o;o>>=1) sv += __shfl_xor_sync(0xffffffffu, sv, o);
  if (lane==0 && w<4) s_red[w]=sv;
  __syncthreads();
  float mu = (s_red[0]+s_red[1]+s_red[2]+s_red[3]) * (1.f/EE);
  float d = v - mu;
  float qv = (tid < EE) ? d*d : 0.f;
  #pragma unroll
  for (int o=16;o;o>>=1) qv += __shfl_xor_sync(0xffffffffu, qv, o);
  __syncthreads();
  if (lane==0 && w<4) s_red[w]=qv;
  __syncthreads();
  float var = (s_red[0]+s_red[1]+s_red[2]+s_red[3]) * (1.f/EE);
  float rs = rsqrtf(var + 1e-5f);
  if (tid < EE){
    s_lnq[tid] = d*rs*lnq_g[tid] + lnq_b[tid];
    float lk = d*rs*lnk_g[tid] + lnk_b[tid];
    s_lnk[tid] = lk;
    if (h == 0) g_lnk[tid] = lk;
  }
  __syncthreads();

  {
    int f = tid & 127, part = tid >> 7;
    float acc = 0.f;
    int e0 = part*16;
    #pragma unroll
    for (int e=0;e<16;e++) acc += s_lnq[e0+e]*Wq[(e0+e)*EE+f];
    s_part[part][f] = acc;
  }
  __syncthreads();
  if (tid < EE){
    float a = 0.f;
    #pragma unroll
    for (int p=0;p<8;p++) a += s_part[p][tid];
    s_q[tid] = a;
  }
  __syncthreads();

  float a_p = 0.f, sx_p = 0.f, c_p = 0.f;
  if (tid < EE){
    int e = tid;
    const float4* wk = (const float4*)(Wk + e*EE + h*HDc);
    const float* qq = &s_q[h*HDc];
    float a = 0.f;
    #pragma unroll
    for (int i=0;i<4;i++){
      float4 wv = wk[i];
      a += qq[i*4+0]*wv.x + qq[i*4+1]*wv.y + qq[i*4+2]*wv.z + qq[i*4+3]*wv.w;
    }
    a *= 0.25f;
    float alg = lnk_g[e]*a;
    g_Alg[h*EE + e] = alg;
    a_p  = s_lnk[e]*a;
    c_p  = lnk_b[e]*a;
    sx_p = alg;
  }
  {
    float aa = a_p, ss = sx_p, cc = c_p;
    #pragma unroll
    for (int o=16;o;o>>=1){
      aa += __shfl_xor_sync(0xffffffffu, aa, o);
      ss += __shfl_xor_sync(0xffffffffu, ss, o);
      cc += __shfl_xor_sync(0xffffffffu, cc, o);
    }
    if (tid < EE && lane == 0){ s_r3[w][0]=aa; s_r3[w][1]=ss; s_r3[w][2]=cc; }
  }
  if (w == 8){
    float kbv = fmaxf(kb1[lane], 0.f) * kW2[lane*HH + h];
    #pragma unroll
    for (int o=16;o;o>>=1) kbv += __shfl_xor_sync(0xffffffffu, kbv, o);
    if (lane == 0) s_kbv = kbv;
  }
  __syncthreads();
  if (tid == 0){
    float a  = s_r3[0][0]+s_r3[1][0]+s_r3[2][0]+s_r3[3][0];
    float sx = s_r3[0][1]+s_r3[1][1]+s_r3[2][1]+s_r3[3][1];
    float c  = s_r3[0][2]+s_r3[1][2]+s_r3[2][2]+s_r3[3][2];
    g_SC[h] = make_float2(sx, c);
    g_dots0[h] = a + kb2[h] + s_kbv;
  }
}

// ---------------- kernel 3: bin points ----------------
__global__ void k_bin(const float* __restrict__ x){
  float mn0=g_min[0], mx0=g_max[0], mn1=g_min[1], mx1=g_max[1];
  float st0 = __fdiv_rn(mx0-mn0, (float)(G1-1));
  float st1 = __fdiv_rn(mx1-mn1, (float)(G2-1));
  const float4* x4 = (const float4*)x;
  for (int i = blockIdx.x*blockDim.x + threadIdx.x; i < BB*NN/2; i += gridDim.x*blockDim.x){
    float4 v = x4[i];
    #pragma unroll
    for (int u=0;u<2;u++){
      float px = u ? v.z : v.x;
      float py = u ? v.w : v.y;
      float f0 = rintf(__fdiv_rn(px-mn0, st0));
      float f1 = rintf(__fdiv_rn(py-mn1, st1));
      f0 = fminf(fmaxf(f0, 0.f), (float)(G1-1));
      f1 = fminf(fmaxf(f1, 0.f), (float)(G2-1));
      int p = 2*i + u;
      int b = p / NN, n = p % NN;
      int t = b*MM + ((int)f0)*G2 + (int)f1;
      int slot = atomicAdd(&g_count[t], 1);
      if (slot < PP) g_ptid[t*PP + slot] = n;
    }
  }
}

// ---------------- kernel 3b: per-point stats + logits (4 pts/warp) ----------------
__global__ void __launch_bounds__(256) k_point(const float* __restrict__ z){
  int warp = threadIdx.x >> 5, lane = threadIdx.x & 31;
  int p0 = (blockIdx.x*8 + warp)*4;

  float4 A[HH];
  #pragma unroll
  for (int h=0;h<HH;h++) A[h] = ((const float4*)(g_Alg + h*EE))[lane];

  float4 zv[4];
  #pragma unroll
  for (int p=0;p<4;p++) zv[p] = ((const float4*)z)[(size_t)(p0+p)*32 + lane];

  float v8[8];
  #pragma unroll
  for (int p=0;p<4;p++){
    float4 a = zv[p];
    v8[2*p]   = a.x+a.y+a.z+a.w;
    v8[2*p+1] = a.x*a.x + a.y*a.y + a.z*a.z + a.w*a.w;
  }
  float r = reduce8(v8, lane);
  float other = __shfl_xor_sync(0xffffffffu, r, 4);
  int g = lane >> 2;
  float s_ = (g & 1) ? other : r;
  float q_ = (g & 1) ? r : other;
  float muv = s_*(1.f/EE);
  float rsv = rsqrtf(q_*(1.f/EE) - muv*muv + 1e-5f);
  if ((lane & 7) == 0) g_stats[p0 + (lane>>3)] = make_float2(muv, rsv);
  float mup[4], rsp[4];
  #pragma unroll
  for (int p=0;p<4;p++){
    mup[p] = __shfl_sync(0xffffffffu, muv, p*8);
    rsp[p] = __shfl_sync(0xffffffffu, rsv, p*8);
  }

  int hh = lane >> 2, sub = lane & 3;
  #pragma unroll
  for (int pp=0; pp<4; pp+=2){
    float d0[HH], d1[HH];
    float4 za = zv[pp], zb = zv[pp+1];
    #pragma unroll
    for (int h=0;h<HH;h++){
      d0[h] = za.x*A[h].x + za.y*A[h].y + za.z*A[h].z + za.w*A[h].w;
      d1[h] = zb.x*A[h].x + zb.y*A[h].y + zb.z*A[h].z + zb.w*A[h].w;
    }
    float r0 = reduce8(d0, lane);
    float r1 = reduce8(d1, lane);
    if (sub == 0){
      float2 sc = g_SC[hh];
      g_plog[(size_t)(p0+pp)*HH + hh] = rsp[pp]*(r0 - mup[pp]*sc.x) + sc.y;
    } else if (sub == 1){
      float2 sc = g_SC[hh];
      g_plog[(size_t)(p0+pp+1)*HH + hh] = rsp[pp+1]*(r1 - mup[pp+1]*sc.x) + sc.y;
    }
  }
}

// ---------------- kernel 4: main fused kernel ----------------
struct Smem {
  float zbar[TB][HH][EE];   // 32KB
  float out[TB][EE];
  float znew[TB][EE];
  float ln2[TB][EE];
  float h1[TB][FFc];
  float p[TB][PP+2][HH];
  float mlp1[KHc][4];
  float kw2s[KHc][HH];
};

// register-blocked weight pass: F=2 features (j, j+64) x T=2 tokens, float4 weights.
// Shared-activation variant (act row independent of feature).
#define WP2(GW, A0ROW, A1ROW, R00, R01, R10, R11) { \
  const ulonglong2* w4 = (const ulonglong2*)(GW); \
  ulonglong2 wa = w4[j], wb = w4[j+64]; \
  unsigned long long a00=0,b00=0,a01=0,b01=0,a10=0,b10=0,a11=0,b11=0; \
  const ulonglong2* A0p = (const ulonglong2*)(A0ROW); \
  const ulonglong2* A1p = (const ulonglong2*)(A1ROW); \
  _Pragma("unroll 8") \
  for (int r4=0;r4<32;r4++){ \
    ulonglong2 na, nb; \
    if (r4+1<32){ na = w4[(r4+1)*128 + j]; nb = w4[(r4+1)*128 + j + 64]; } \
    ulonglong2 x0 = A0p[r4], x1 = A1p[r4]; \
    fma2(a00, x0.x, wa.x); fma2(b00, x0.y, wa.y); \
    fma2(a01, x1.x, wa.x); fma2(b01, x1.y, wa.y); \
    fma2(a10, x0.x, wb.x); fma2(b10, x0.y, wb.y); \
    fma2(a11, x1.x, wb.x); fma2(b11, x1.y, wb.y); \
    wa = na; wb = nb; \
  } \
  R00 = unpack_sum(a00)+unpack_sum(b00); \
  R01 = unpack_sum(a01)+unpack_sum(b01); \
  R10 = unpack_sum(a10)+unpack_sum(b10); \
  R11 = unpack_sum(a11)+unpack_sum(b11); \
}

// W1 variant: activation row depends on feature's head (h0 for f0, h1 for f1).
#define WP1(GW, A0H0, A1H0, A0H1, A1H1, R00, R01, R10, R11) { \
  const ulonglong2* w4 = (const ulonglong2*)(GW); \
  ulonglong2 wa = w4[j], wb = w4[j+64]; \
  unsigned long long a00=0,b00=0,a01=0,b01=0,a10=0,b10=0,a11=0,b11=0; \
  const ulonglong2* A0h0 = (const ulonglong2*)(A0H0); \
  const ulonglong2* A1h0 = (const ulonglong2*)(A1H0); \
  const ulonglong2* A0h1 = (const ulonglong2*)(A0H1); \
  const ulonglong2* A1h1 = (const ulonglong2*)(A1H1); \
  _Pragma("unroll 8") \
  for (int r4=0;r4<32;r4++){ \
    ulonglong2 na, nb; \
    if (r4+1<32){ na = w4[(r4+1)*128 + j]; nb = w4[(r4+1)*128 + j + 64]; } \
    ulonglong2 x00 = A0h0[r4], x10 = A1h0[r4]; \
    ulonglong2 x01 = A0h1[r4], x11 = A1h1[r4]; \
    fma2(a00, x00.x, wa.x); fma2(b00, x00.y, wa.y); \
    fma2(a01, x10.x, wa.x); fma2(b01, x10.y, wa.y); \
    fma2(a10, x01.x, wb.x); fma2(b10, x01.y, wb.y); \
    fma2(a11, x11.x, wb.x); fma2(b11, x11.y, wb.y); \
    wa = na; wb = nb; \
  } \
  R00 = unpack_sum(a00)+unpack_sum(b00); \
  R01 = unpack_sum(a01)+unpack_sum(b01); \
  R10 = unpack_sum(a10)+unpack_sum(b10); \
  R11 = unpack_sum(a11)+unpack_sum(b11); \
}

__global__ void __launch_bounds__(256, 3) k_main(
    const float* __restrict__ x, const float* __restrict__ z,
    const float* __restrict__ latent,
    const float* __restrict__ bo,
    const float* __restrict__ kW1, const float* __restrict__ kb1,
    const float* __restrict__ kW2, const float* __restrict__ kb2,
    const float* __restrict__ lnk_g, const float* __restrict__ lnk_b,
    const float* __restrict__ ln2_g, const float* __restrict__ ln2_b,
    const float* __restrict__ fb1, const float* __restrict__ fb2,
    float* __restrict__ out_x, float* __restrict__ out_z)
{
  extern __shared__ Smem S[];
  Smem* s = S;
  int tid = threadIdx.x, lane = tid & 31, warp = tid >> 5;
  int t0 = blockIdx.x * TB;
  int b  = t0 >> 10;

  if (tid < KHc){
    s->mlp1[tid][0] = kW1[tid];
    s->mlp1[tid][1] = kW1[KHc+tid];
    s->mlp1[tid][2] = kb1[tid];
    s->mlp1[tid][3] = 0.f;
  }
  { int jj = tid >> 3, hx = tid & 7; s->kw2s[jj][hx] = kW2[jj*HH + hx]; }
  __syncthreads();

  float mn0=g_min[0], mx0=g_max[0], mn1=g_min[1], mx1=g_max[1];
  float st0 = __fdiv_rn(mx0-mn0, (float)(G1-1));
  float st1 = __fdiv_rn(mx1-mn1, (float)(G2-1));

  // ============ token phase: warp owns token t0+warp ============
  {
    int tg = t0 + warp;
    int cell = tg & (MM-1);
    int c1 = cell >> 5, c2 = cell & 31;
    float xg0 = (c1==G1-1) ? mx0 : (mn0 + (float)c1*st0);
    float xg1 = (c2==G2-1) ? mx1 : (mn1 + (float)c2*st1);
    int cnt = g_count[tg]; if (cnt > PP) cnt = PP;
    bool act = lane < cnt;

    int nid = 0; float2 xv = make_float2(0.f, 0.f);
    float2 stats = make_float2(0.f, 1.f);
    if (act){
      nid = g_ptid[tg*PP + lane];
      xv = ((const float2*)x)[(size_t)b*NN + nid];
      stats = g_stats[b*NN + nid];
    }

    // ---- pass 1: per-key logits in registers ----
    float pl[HH];
    if (act){
      const float4* pv = (const float4*)(g_plog + (size_t)(b*NN+nid)*HH);
      float4 pa = pv[0], pb = pv[1];
      pl[0]=pa.x; pl[1]=pa.y; pl[2]=pa.z; pl[3]=pa.w;
      pl[4]=pb.x; pl[5]=pb.y; pl[6]=pb.z; pl[7]=pb.w;
      float dx0 = xv.x - xg0, dx1 = xv.y - xg1;
      #pragma unroll 8
      for (int jj=0;jj<KHc;jj++){
        float4 m1 = *(const float4*)s->mlp1[jj];
        float hv = fmaxf(fmaf(dx0, m1.x, fmaf(dx1, m1.y, m1.z)), 0.f);
        float4 w2a = *(const float4*)&s->kw2s[jj][0];
        float4 w2b = *(const float4*)&s->kw2s[jj][4];
        pl[0]=fmaf(hv,w2a.x,pl[0]); pl[1]=fmaf(hv,w2a.y,pl[1]);
        pl[2]=fmaf(hv,w2a.z,pl[2]); pl[3]=fmaf(hv,w2a.w,pl[3]);
        pl[4]=fmaf(hv,w2b.x,pl[4]); pl[5]=fmaf(hv,w2b.y,pl[5]);
        pl[6]=fmaf(hv,w2b.z,pl[6]); pl[7]=fmaf(hv,w2b.w,pl[7]);
      }
    } else {
      #pragma unroll
      for (int h=0;h<HH;h++) pl[h] = -1e30f;
    }

    // ---- softmax ----
    int hh = lane >> 2;
    float d0h = g_dots0[hh];
    float m = reduce8_max(pl, lane);
    m = fmaxf(m, d0h);
    if ((lane & 3) == 0) s->p[warp][PP+1][hh] = m;
    __syncwarp();
    float4 ma4 = *(const float4*)&s->p[warp][PP+1][0];
    float4 mb4 = *(const float4*)&s->p[warp][PP+1][4];
    float mm[HH] = {ma4.x,ma4.y,ma4.z,ma4.w,mb4.x,mb4.y,mb4.z,mb4.w};
    float e[HH];
    #pragma unroll
    for (int h=0;h<HH;h++) e[h] = __expf(pl[h]-mm[h]);
    float ssum = reduce8(e, lane);
    float e0 = __expf(d0h - m);
    float inv = 1.f/(ssum + e0);
    __syncwarp();
    if ((lane & 3) == 0){
      s->p[warp][PP+1][hh] = inv;
      s->p[warp][0][hh] = e0*inv;
    }
    __syncwarp();
    float4 ia4 = *(const float4*)&s->p[warp][PP+1][0];
    float4 ib4 = *(const float4*)&s->p[warp][PP+1][4];
    float ii[HH] = {ia4.x,ia4.y,ia4.z,ia4.w,ib4.x,ib4.y,ib4.z,ib4.w};
    float p8[HH];
    #pragma unroll
    for (int h=0;h<HH;h++) p8[h] = e[h]*ii[h];
    if (act){
      float4* prow = (float4*)s->p[warp][lane+1];
      prow[0] = make_float4(p8[0],p8[1],p8[2],p8[3]);
      prow[1] = make_float4(p8[4],p8[5],p8[6],p8[7]);
    }
    __syncwarp();

    // ---- TE x-update ----
    {
      float ma = 0.125f*(p8[0]+p8[1]+p8[2]+p8[3]+p8[4]+p8[5]+p8[6]+p8[7]);
      float c0 = ma*xv.x, c1v = ma*xv.y;
      if (lane == 0){
        float4 pa = *(const float4*)&s->p[warp][0][0];
        float4 pb = *(const float4*)&s->p[warp][0][4];
        float ma0 = 0.125f*(pa.x+pa.y+pa.z+pa.w+pb.x+pb.y+pb.z+pb.w);
        c0 += ma0*xg0; c1v += ma0*xg1;
      }
      #pragma unroll
      for (int o=16;o;o>>=1){
        c0  += __shfl_xor_sync(0xffffffffu, c0, o);
        c1v += __shfl_xor_sync(0xffffffffu, c1v, o);
      }
      if (lane == 0){
        out_x[(size_t)tg*2]   = c0;
        out_x[(size_t)tg*2+1] = c1v;
      }
    }

    // ---- pass 2: zbar ----
    {
      float4 lg = ((const float4*)lnk_g)[lane];
      float4 lb = ((const float4*)lnk_b)[lane];
      float4 lnkv = ((const float4*)g_lnk)[lane];
      float4 p0a = *(const float4*)&s->p[warp][0][0];
      float4 p0b = *(const float4*)&s->p[warp][0][4];
      float4 acc[HH];
      acc[0]=make_float4(p0a.x*lnkv.x,p0a.x*lnkv.y,p0a.x*lnkv.z,p0a.x*lnkv.w);
      acc[1]=make_float4(p0a.y*lnkv.x,p0a.y*lnkv.y,p0a.y*lnkv.z,p0a.y*lnkv.w);
      acc[2]=make_float4(p0a.z*lnkv.x,p0a.z*lnkv.y,p0a.z*lnkv.z,p0a.z*lnkv.w);
      acc[3]=make_float4(p0a.w*lnkv.x,p0a.w*lnkv.y,p0a.w*lnkv.z,p0a.w*lnkv.w);
      acc[4]=make_float4(p0b.x*lnkv.x,p0b.x*lnkv.y,p0b.x*lnkv.z,p0b.x*lnkv.w);
      acc[5]=make_float4(p0b.y*lnkv.x,p0b.y*lnkv.y,p0b.y*lnkv.z,p0b.y*lnkv.w);
      acc[6]=make_float4(p0b.z*lnkv.x,p0b.z*lnkv.y,p0b.z*lnkv.z,p0b.z*lnkv.w);
      acc[7]=make_float4(p0b.w*lnkv.x,p0b.w*lnkv.y,p0b.w*lnkv.z,p0b.w*lnkv.w);
      float4 vbuf0, vbuf1;
      if (cnt > 0){
        int n = __shfl_sync(0xffffffffu, nid, 0);
        vbuf0 = ((const float4*)z)[(size_t)(b*NN+n)*32 + lane];
      }
      for (int k=0;k<cnt;k++){
        if (k+1 < cnt){
          int n = __shfl_sync(0xffffffffu, nid, k+1);
          vbuf1 = ((const float4*)z)[(size_t)(b*NN+n)*32 + lane];
        }
        float4 v = vbuf0;
        float mu = __shfl_sync(0xffffffffu, stats.x, k);
        float rs = __shfl_sync(0xffffffffu, stats.y, k);
        float z0=(v.x-mu)*rs*lg.x+lb.x, z1=(v.y-mu)*rs*lg.y+lb.y;
        float z2=(v.z-mu)*rs*lg.z+lb.z, z3=(v.w-mu)*rs*lg.w+lb.w;
        float4 pa = *(const float4*)&s->p[warp][k+1][0];
        float4 pb = *(const float4*)&s->p[warp][k+1][4];
        float pk[HH] = {pa.x,pa.y,pa.z,pa.w,pb.x,pb.y,pb.z,pb.w};
        #pragma unroll
        for (int h=0;h<HH;h++){
          acc[h].x = fmaf(pk[h], z0, acc[h].x);
          acc[h].y = fmaf(pk[h], z1, acc[h].y);
          acc[h].z = fmaf(pk[h], z2, acc[h].z);
          acc[h].w = fmaf(pk[h], z3, acc[h].w);
        }
        vbuf0 = vbuf1;
      }
      #pragma unroll
      for (int h=0;h<HH;h++)
        ((float4*)s->zbar[warp][h])[lane] = acc[h];
    }
  }
  __syncthreads();

  // ============ weight passes: F=2 x T=2 register blocking ============
  int j  = tid & 63;         // feature low index
  int tg4 = tid >> 6;        // token group 0..3
  int f0 = j, f1 = j + 64;
  int ta = tg4*2, tb = tg4*2 + 1;
  int h0 = j >> 4, h1 = h0 + 4;

  // ---- W1: out = zbar . Wv ----
  {
    float r00, r01, r10, r11;
    WP1(g_pWv4, s->zbar[ta][h0], s->zbar[tb][h0], s->zbar[ta][h1], s->zbar[tb][h1],
        r00, r01, r10, r11)
    s->out[ta][f0] = r00; s->out[tb][f0] = r01;
    s->out[ta][f1] = r10; s->out[tb][f1] = r11;
  }
  __syncthreads();

  // ---- W2: znew = latent + out @ Wo + bo ----
  {
    float r00, r01, r10, r11;
    WP2(g_pWo4, s->out[ta], s->out[tb], r00, r01, r10, r11)
    float base0 = latent[f0] + bo[f0];
    float base1 = latent[f1] + bo[f1];
    s->znew[ta][f0] = base0 + r00; s->znew[tb][f0] = base0 + r01;
    s->znew[ta][f1] = base1 + r10; s->znew[tb][f1] = base1 + r11;
  }
  __syncthreads();

  // ---- LN2: warp per token ----
  {
    float4 g2 = ((const float4*)ln2_g)[lane];
    float4 b2 = ((const float4*)ln2_b)[lane];
    int t = warp;
    float4 v = ((const float4*)s->znew[t])[lane];
    float sv = v.x+v.y+v.z+v.w;
    #pragma unroll
    for (int o=16;o;o>>=1) sv += __shfl_xor_sync(0xffffffffu, sv, o);
    float mu = sv*(1.f/EE);
    float d0=v.x-mu, d1=v.y-mu, d2=v.z-mu, d3=v.w-mu;
    float q = d0*d0+d1*d1+d2*d2+d3*d3;
    #pragma unroll
    for (int o=16;o;o>>=1) q += __shfl_xor_sync(0xffffffffu, q, o);
    float rs = rsqrtf(q*(1.f/EE)+1e-5f);
    ((float4*)s->ln2[t])[lane] = make_float4(d0*rs*g2.x+b2.x, d1*rs*g2.y+b2.y,
                                             d2*rs*g2.z+b2.z, d3*rs*g2.w+b2.w);
  }
  __syncthreads();

  // ---- FFN1 ----
  {
    float r00, r01, r10, r11;
    WP2(g_pW14, s->ln2[ta], s->ln2[tb], r00, r01, r10, r11)
    float b0v = fb1[f0], b1v = fb1[f1];
    s->h1[ta][f0] = fmaxf(r00 + b0v, 0.f); s->h1[tb][f0] = fmaxf(r01 + b0v, 0.f);
    s->h1[ta][f1] = fmaxf(r10 + b1v, 0.f); s->h1[tb][f1] = fmaxf(r11 + b1v, 0.f);
  }
  __syncthreads();

  // ---- FFN2 + residual ----
  {
    float r00, r01, r10, r11;
    WP2(g_pW24, s->h1[ta], s->h1[tb], r00, r01, r10, r11)
    float b0v = fb2[f0], b1v = fb2[f1];
    out_z[(size_t)(t0+ta)*EE + f0] = s->znew[ta][f0] + r00 + b0v;
    out_z[(size_t)(t0+tb)*EE + f0] = s->znew[tb][f0] + r01 + b0v;
    out_z[(size_t)(t0+ta)*EE + f1] = s->znew[ta][f1] + r10 + b1v;
    out_z[(size_t)(t0+tb)*EE + f1] = s->znew[tb][f1] + r11 + b1v;
  }
}

// ---------------- launch ----------------
static cudaStream_t get_aux_stream(){
  static cudaStream_t s = [](){
    cudaStream_t st; cudaStreamCreateWithFlags(&st, cudaStreamNonBlocking); return st;
  }();
  return s;
}
static cudaEvent_t get_event(int which){
  static cudaEvent_t e0 = [](){
    cudaEvent_t e; cudaEventCreateWithFlags(&e, cudaEventDisableTiming); return e;
  }();
  static cudaEvent_t e1 = [](){
    cudaEvent_t e; cudaEventCreateWithFlags(&e, cudaEventDisableTiming); return e;
  }();
  return which ? e1 : e0;
}

extern "C" void kernel_launch(void* const* d_in, const int* in_sizes, int n_in,
                              void* d_out, int out_size){
  const float* x     = (const float*)d_in[0];
  const float* z     = (const float*)d_in[1];
  const float* latent= (const float*)d_in[6];
  const float* Wq    = (const float*)d_in[7];
  const float* Wk    = (const float*)d_in[8];
  const float* Wv    = (const float*)d_in[9];
  const float* Wo    = (const float*)d_in[10];
  const float* bo    = (const float*)d_in[11];
  const float* kW1   = (const float*)d_in[12];
  const float* kb1   = (const float*)d_in[13];
  const float* kW2   = (const float*)d_in[14];
  const float* kb2   = (const float*)d_in[15];
  const float* lnq_g = (const float*)d_in[16];
  const float* lnq_b = (const float*)d_in[17];
  const float* lnk_g = (const float*)d_in[18];
  const float* lnk_b = (const float*)d_in[19];
  const float* ln2_g = (const float*)d_in[20];
  const float* ln2_b = (const float*)d_in[21];
  const float* fW1   = (const float*)d_in[22];
  const float* fb1   = (const float*)d_in[23];
  const float* fW2   = (const float*)d_in[24];
  const float* fb2   = (const float*)d_in[25];

  float* out   = (float*)d_out;
  float* out_x = out;
  float* out_z = out + (size_t)TT*DXc;

  static_assert(sizeof(Smem) < 75*1024, "smem");
  cudaFuncSetAttribute(k_main, cudaFuncAttributeMaxDynamicSharedMemorySize, (int)sizeof(Smem));

  cudaStream_t aux = get_aux_stream();
  cudaEvent_t ev_fork = get_event(0), ev_join = get_event(1);

  cudaEventRecord(ev_fork, 0);
  cudaStreamWaitEvent(aux, ev_fork, 0);

  // default stream: k_pre -> k_minmax -> k_bin
  k_pre<<<32, 256>>>(Wv, Wo, fW1, fW2);
  k_minmax<<<128, 256>>>(x);
  k_bin<<<128, 256>>>(x);

  // aux stream: k_prep -> k_point
  k_prep<<<HH, 1024, 0, aux>>>(latent, Wq, Wk, lnq_g, lnq_b, lnk_g, lnk_b, kb1, kW2, kb2);
  k_point<<<BB*NN/32, 256, 0, aux>>>(z);

  cudaEventRecord(ev_join, aux);
  cudaStreamWaitEvent(0, ev_join, 0);

  k_main<<<TT/TB, 256, sizeof(Smem)>>>(x, z, latent, bo, kW1, kb1, kW2, kb2,
                                       lnk_g, lnk_b, ln2_g, ln2_b, fb1, fb2,
                                       out_x, out_z);
}

// round 16
// speedup vs baseline: 1.1464x; 1.1464x over previous
#include <cuda_runtime.h>
#include <math.h>

#define BB 8
#define NN 8192
#define DXc 2
#define EE 128
#define HH 8
#define HDc 16
#define KHc 32
#define FFc 128
#define G1 32
#define G2 32
#define PP 32
#define MM (G1*G2)      // 1024
#define TT (BB*MM)      // 8192
#define TB 8            // tokens per block (one warp per token)

// ---------------- device scratch ----------------
__device__ float g_min[2];
__device__ float g_max[2];
__device__ int   g_count[TT];
__device__ int   g_ptid[TT*PP];
__device__ float g_Alg[HH*EE];      // [h][e] = lnk_g[e]*qWkT[h][e] (qWkT pre-scaled 0.25)
__device__ float2 g_SC[HH];         // (S_h, C_h)
__device__ float g_lnk[EE];         // LN_k(latent)
__device__ float g_dots0[HH];
__device__ float2 g_stats[BB*NN];   // per-point (mu, rs)
__device__ float g_plog[BB*NN*HH];  // per-point q-folded logits
__device__ float2 g_pWv[EE/2*EE];   // packed (W[e][f], W[e+1][f])
__device__ float2 g_pWo[EE/2*EE];
__device__ float2 g_pW1[EE/2*FFc];
__device__ float2 g_pW2[FFc/2*EE];

// ---------------- helpers ----------------
__device__ __forceinline__ void atomicMinF(float* addr, float v){
  if (v >= 0.f) atomicMin((int*)addr, __float_as_int(v));
  else          atomicMax((unsigned int*)addr, __float_as_uint(v));
}
__device__ __forceinline__ void atomicMaxF(float* addr, float v){
  if (v >= 0.f) atomicMax((int*)addr, __float_as_int(v));
  else          atomicMin((unsigned int*)addr, __float_as_uint(v));
}
__device__ __forceinline__ void fma2(unsigned long long &d, unsigned long long a, unsigned long long b){
  asm("fma.rn.f32x2 %0, %1, %2, %0;" : "+l"(d) : "l"(a), "l"(b));
}
__device__ __forceinline__ float unpack_sum(unsigned long long v){
  float lo, hi;
  asm("mov.b64 {%0,%1}, %2;" : "=f"(lo), "=f"(hi) : "l"(v));
  return lo + hi;
}
// lane-specialized reduce (sum) of 8 values
__device__ __forceinline__ float reduce8(const float* v, int lane){
  float sh[8];
  #pragma unroll
  for (int i=0;i<8;i++) sh[i] = __shfl_xor_sync(0xffffffffu, v[i], 16);
  float a[4];
  bool hi4 = (lane & 16) != 0;
  #pragma unroll
  for (int i=0;i<4;i++) a[i] = hi4 ? (v[i+4]+sh[i+4]) : (v[i]+sh[i]);
  float bsh[4];
  #pragma unroll
  for (int i=0;i<4;i++) bsh[i] = __shfl_xor_sync(0xffffffffu, a[i], 8);
  float b[2];
  bool hi2 = (lane & 8) != 0;
  #pragma unroll
  for (int i=0;i<2;i++) b[i] = hi2 ? (a[i+2]+bsh[i+2]) : (a[i]+bsh[i]);
  float c0 = __shfl_xor_sync(0xffffffffu, b[0], 4);
  float c1 = __shfl_xor_sync(0xffffffffu, b[1], 4);
  float c = (lane & 4) ? (b[1]+c1) : (b[0]+c0);
  c += __shfl_xor_sync(0xffffffffu, c, 2);
  c += __shfl_xor_sync(0xffffffffu, c, 1);
  return c;
}
// same, but max
__device__ __forceinline__ float reduce8_max(const float* v, int lane){
  float sh[8];
  #pragma unroll
  for (int i=0;i<8;i++) sh[i] = __shfl_xor_sync(0xffffffffu, v[i], 16);
  float a[4];
  bool hi4 = (lane & 16) != 0;
  #pragma unroll
  for (int i=0;i<4;i++) a[i] = hi4 ? fmaxf(v[i+4],sh[i+4]) : fmaxf(v[i],sh[i]);
  float bsh[4];
  #pragma unroll
  for (int i=0;i<4;i++) bsh[i] = __shfl_xor_sync(0xffffffffu, a[i], 8);
  float b[2];
  bool hi2 = (lane & 8) != 0;
  #pragma unroll
  for (int i=0;i<2;i++) b[i] = hi2 ? fmaxf(a[i+2],bsh[i+2]) : fmaxf(a[i],bsh[i]);
  float c0 = __shfl_xor_sync(0xffffffffu, b[0], 4);
  float c1 = __shfl_xor_sync(0xffffffffu, b[1], 4);
  float c = (lane & 4) ? fmaxf(b[1],c1) : fmaxf(b[0],c0);
  c = fmaxf(c, __shfl_xor_sync(0xffffffffu, c, 2));
  c = fmaxf(c, __shfl_xor_sync(0xffffffffu, c, 1));
  return c;
}

// ---------------- kernel 0: init + pack weights ----------------
__global__ void k_pre(const float* __restrict__ Wv, const float* __restrict__ Wo,
                      const float* __restrict__ fW1, const float* __restrict__ fW2){
  int i = blockIdx.x*blockDim.x + threadIdx.x;   // 0..8191
  g_count[i] = 0;
  if (i < 2){
    g_min[i] = __int_as_float(0x7f800000);
    g_max[i] = __int_as_float(0xff800000);
  }
  int r = i >> 7, f = i & 127;
  int e0 = 2*r;
  g_pWv[i] = make_float2(Wv[e0*EE+f],   Wv[(e0+1)*EE+f]);
  g_pWo[i] = make_float2(Wo[e0*EE+f],   Wo[(e0+1)*EE+f]);
  g_pW1[i] = make_float2(fW1[e0*FFc+f], fW1[(e0+1)*FFc+f]);
  g_pW2[i] = make_float2(fW2[e0*EE+f],  fW2[(e0+1)*EE+f]);
}

// ---------------- kernel 1: global min/max ----------------
__global__ void k_minmax(const float* __restrict__ x){
  float mn0=1e38f, mn1=1e38f, mx0=-1e38f, mx1=-1e38f;
  const float4* x4 = (const float4*)x;
  for (int i = blockIdx.x*blockDim.x + threadIdx.x; i < BB*NN/2; i += gridDim.x*blockDim.x){
    float4 v = x4[i];
    mn0 = fminf(mn0, fminf(v.x, v.z)); mx0 = fmaxf(mx0, fmaxf(v.x, v.z));
    mn1 = fminf(mn1, fminf(v.y, v.w)); mx1 = fmaxf(mx1, fmaxf(v.y, v.w));
  }
  #pragma unroll
  for (int o=16;o;o>>=1){
    mn0 = fminf(mn0, __shfl_xor_sync(0xffffffffu, mn0, o));
    mx0 = fmaxf(mx0, __shfl_xor_sync(0xffffffffu, mx0, o));
    mn1 = fminf(mn1, __shfl_xor_sync(0xffffffffu, mn1, o));
    mx1 = fmaxf(mx1, __shfl_xor_sync(0xffffffffu, mx1, o));
  }
  __shared__ float s[4][8];
  int w = threadIdx.x>>5, l = threadIdx.x&31;
  if (l==0){ s[0][w]=mn0; s[1][w]=mx0; s[2][w]=mn1; s[3][w]=mx1; }
  __syncthreads();
  if (threadIdx.x==0){
    int nw = blockDim.x>>5;
    float a=s[0][0], b=s[1][0], c=s[2][0], d=s[3][0];
    for (int j=1;j<nw;j++){ a=fminf(a,s[0][j]); b=fmaxf(b,s[1][j]); c=fminf(c,s[2][j]); d=fmaxf(d,s[3][j]); }
    atomicMinF(&g_min[0], a); atomicMaxF(&g_max[0], b);
    atomicMinF(&g_min[1], c); atomicMaxF(&g_max[1], d);
  }
}

// ---------------- kernel 2: precompute (8 blocks, block = head) ----------------
__global__ void __launch_bounds__(1024) k_prep(
    const float* __restrict__ latent,
    const float* __restrict__ Wq, const float* __restrict__ Wk,
    const float* __restrict__ lnq_g, const float* __restrict__ lnq_b,
    const float* __restrict__ lnk_g, const float* __restrict__ lnk_b,
    const float* __restrict__ kb1, const float* __restrict__ kW2,
    const float* __restrict__ kb2){
  __shared__ float s_lnq[EE], s_lnk[EE], s_q[EE];
  __shared__ float s_part[8][EE];
  __shared__ float s_red[8];
  __shared__ float s_r3[4][3];
  __shared__ float s_kbv;
  int tid = threadIdx.x, lane = tid & 31, w = tid >> 5;
  int h = blockIdx.x;

  float v = (tid < EE) ? latent[tid] : 0.f;
  float sv = v;
  #pragma unroll
  for (int o=16;o;o>>=1) sv += __shfl_xor_sync(0xffffffffu, sv, o);
  if (lane==0 && w<4) s_red[w]=sv;
  __syncthreads();
  float mu = (s_red[0]+s_red[1]+s_red[2]+s_red[3]) * (1.f/EE);
  float d = v - mu;
  float qv = (tid < EE) ? d*d : 0.f;
  #pragma unroll
  for (int o=16;o;o>>=1) qv += __shfl_xor_sync(0xffffffffu, qv, o);
  __syncthreads();
  if (lane==0 && w<4) s_red[w]=qv;
  __syncthreads();
  float var = (s_red[0]+s_red[1]+s_red[2]+s_red[3]) * (1.f/EE);
  float rs = rsqrtf(var + 1e-5f);
  if (tid < EE){
    s_lnq[tid] = d*rs*lnq_g[tid] + lnq_b[tid];
    float lk = d*rs*lnk_g[tid] + lnk_b[tid];
    s_lnk[tid] = lk;
    if (h == 0) g_lnk[tid] = lk;
  }
  __syncthreads();

  {
    int f = tid & 127, part = tid >> 7;
    float acc = 0.f;
    int e0 = part*16;
    #pragma unroll
    for (int e=0;e<16;e++) acc += s_lnq[e0+e]*Wq[(e0+e)*EE+f];
    s_part[part][f] = acc;
  }
  __syncthreads();
  if (tid < EE){
    float a = 0.f;
    #pragma unroll
    for (int p=0;p<8;p++) a += s_part[p][tid];
    s_q[tid] = a;
  }
  __syncthreads();

  float a_p = 0.f, sx_p = 0.f, c_p = 0.f;
  if (tid < EE){
    int e = tid;
    const float4* wk = (const float4*)(Wk + e*EE + h*HDc);
    const float* qq = &s_q[h*HDc];
    float a = 0.f;
    #pragma unroll
    for (int i=0;i<4;i++){
      float4 wv = wk[i];
      a += qq[i*4+0]*wv.x + qq[i*4+1]*wv.y + qq[i*4+2]*wv.z + qq[i*4+3]*wv.w;
    }
    a *= 0.25f;
    float alg = lnk_g[e]*a;
    g_Alg[h*EE + e] = alg;
    a_p  = s_lnk[e]*a;
    c_p  = lnk_b[e]*a;
    sx_p = alg;
  }
  {
    float aa = a_p, ss = sx_p, cc = c_p;
    #pragma unroll
    for (int o=16;o;o>>=1){
      aa += __shfl_xor_sync(0xffffffffu, aa, o);
      ss += __shfl_xor_sync(0xffffffffu, ss, o);
      cc += __shfl_xor_sync(0xffffffffu, cc, o);
    }
    if (tid < EE && lane == 0){ s_r3[w][0]=aa; s_r3[w][1]=ss; s_r3[w][2]=cc; }
  }
  if (w == 8){
    float kbv = fmaxf(kb1[lane], 0.f) * kW2[lane*HH + h];
    #pragma unroll
    for (int o=16;o;o>>=1) kbv += __shfl_xor_sync(0xffffffffu, kbv, o);
    if (lane == 0) s_kbv = kbv;
  }
  __syncthreads();
  if (tid == 0){
    float a  = s_r3[0][0]+s_r3[1][0]+s_r3[2][0]+s_r3[3][0];
    float sx = s_r3[0][1]+s_r3[1][1]+s_r3[2][1]+s_r3[3][1];
    float c  = s_r3[0][2]+s_r3[1][2]+s_r3[2][2]+s_r3[3][2];
    g_SC[h] = make_float2(sx, c);
    g_dots0[h] = a + kb2[h] + s_kbv;
  }
}

// ---------------- kernel 3: bin points ----------------
__global__ void k_bin(const float* __restrict__ x){
  float mn0=g_min[0], mx0=g_max[0], mn1=g_min[1], mx1=g_max[1];
  float st0 = __fdiv_rn(mx0-mn0, (float)(G1-1));
  float st1 = __fdiv_rn(mx1-mn1, (float)(G2-1));
  const float4* x4 = (const float4*)x;
  for (int i = blockIdx.x*blockDim.x + threadIdx.x; i < BB*NN/2; i += gridDim.x*blockDim.x){
    float4 v = x4[i];
    #pragma unroll
    for (int u=0;u<2;u++){
      float px = u ? v.z : v.x;
      float py = u ? v.w : v.y;
      float f0 = rintf(__fdiv_rn(px-mn0, st0));
      float f1 = rintf(__fdiv_rn(py-mn1, st1));
      f0 = fminf(fmaxf(f0, 0.f), (float)(G1-1));
      f1 = fminf(fmaxf(f1, 0.f), (float)(G2-1));
      int p = 2*i + u;
      int b = p / NN, n = p % NN;
      int t = b*MM + ((int)f0)*G2 + (int)f1;
      int slot = atomicAdd(&g_count[t], 1);
      if (slot < PP) g_ptid[t*PP + slot] = n;
    }
  }
}

// ---------------- kernel 3b: per-point stats + logits (4 pts/warp) ----------------
__global__ void __launch_bounds__(256) k_point(const float* __restrict__ z){
  int warp = threadIdx.x >> 5, lane = threadIdx.x & 31;
  int p0 = (blockIdx.x*8 + warp)*4;

  float4 A[HH];
  #pragma unroll
  for (int h=0;h<HH;h++) A[h] = ((const float4*)(g_Alg + h*EE))[lane];

  float4 zv[4];
  #pragma unroll
  for (int p=0;p<4;p++) zv[p] = ((const float4*)z)[(size_t)(p0+p)*32 + lane];

  float v8[8];
  #pragma unroll
  for (int p=0;p<4;p++){
    float4 a = zv[p];
    v8[2*p]   = a.x+a.y+a.z+a.w;
    v8[2*p+1] = a.x*a.x + a.y*a.y + a.z*a.z + a.w*a.w;
  }
  float r = reduce8(v8, lane);
  float other = __shfl_xor_sync(0xffffffffu, r, 4);
  int g = lane >> 2;
  float s_ = (g & 1) ? other : r;
  float q_ = (g & 1) ? r : other;
  float muv = s_*(1.f/EE);
  float rsv = rsqrtf(q_*(1.f/EE) - muv*muv + 1e-5f);
  if ((lane & 7) == 0) g_stats[p0 + (lane>>3)] = make_float2(muv, rsv);
  float mup[4], rsp[4];
  #pragma unroll
  for (int p=0;p<4;p++){
    mup[p] = __shfl_sync(0xffffffffu, muv, p*8);
    rsp[p] = __shfl_sync(0xffffffffu, rsv, p*8);
  }

  int hh = lane >> 2, sub = lane & 3;
  #pragma unroll
  for (int pp=0; pp<4; pp+=2){
    float d0[HH], d1[HH];
    float4 za = zv[pp], zb = zv[pp+1];
    #pragma unroll
    for (int h=0;h<HH;h++){
      d0[h] = za.x*A[h].x + za.y*A[h].y + za.z*A[h].z + za.w*A[h].w;
      d1[h] = zb.x*A[h].x + zb.y*A[h].y + zb.z*A[h].z + zb.w*A[h].w;
    }
    float r0 = reduce8(d0, lane);
    float r1 = reduce8(d1, lane);
    if (sub == 0){
      float2 sc = g_SC[hh];
      g_plog[(size_t)(p0+pp)*HH + hh] = rsp[pp]*(r0 - mup[pp]*sc.x) + sc.y;
    } else if (sub == 1){
      float2 sc = g_SC[hh];
      g_plog[(size_t)(p0+pp+1)*HH + hh] = rsp[pp+1]*(r1 - mup[pp+1]*sc.x) + sc.y;
    }
  }
}

// ---------------- kernel 4: main fused kernel (occ 4 via aliased smem) ----------------
struct Smem {
  float zbar[TB][HH][EE];   // 32 KB
  float out[TB][EE];        // 4 KB
  float znew[TB][EE];       // 4 KB
  float p[TB][PP+2][HH];    // 8.5 KB; after token phase aliased as ln2[TB][EE] + h1[TB][EE]
  float mlp1[KHc][4];
  float kw2s[KHc][HH];
};

// depth-4 software-pipelined weight pass (R11 form)
#define WPASS_PROLOG(PW) \
    unsigned long long accA[4] = {0,0,0,0}, accB[4] = {0,0,0,0}; \
    const unsigned long long* pw = (const unsigned long long*)(PW); \
    unsigned long long w0 = pw[f], w1 = pw[128 + f]; \
    unsigned long long w2 = pw[256 + f], w3 = pw[384 + f];

#define WPASS_LOOP(SRC_BASE) \
    for (int r = 0; r < 64; r += 4){ \
      unsigned long long n0=0, n1=0, n2=0, n3=0; \
      int rn = r + 4; \
      if (rn < 64){ \
        n0 = pw[rn*128 + f];     n1 = pw[(rn+1)*128 + f]; \
        n2 = pw[(rn+2)*128 + f]; n3 = pw[(rn+3)*128 + f]; \
      } \
      _Pragma("unroll") \
      for (int i = 0; i < 4; i++){ \
        ulonglong2 va = *(const ulonglong2*)&(SRC_BASE)[2*r]; \
        ulonglong2 vb = *(const ulonglong2*)&(SRC_BASE)[2*r + 4]; \
        fma2(accA[i], va.x, w0); \
        fma2(accB[i], va.y, w1); \
        fma2(accA[i], vb.x, w2); \
        fma2(accB[i], vb.y, w3); \
      } \
      w0 = n0; w1 = n1; w2 = n2; w3 = n3; \
    }

__global__ void __launch_bounds__(256, 4) k_main(
    const float* __restrict__ x, const float* __restrict__ z,
    const float* __restrict__ latent,
    const float* __restrict__ bo,
    const float* __restrict__ kW1, const float* __restrict__ kb1,
    const float* __restrict__ kW2, const float* __restrict__ kb2,
    const float* __restrict__ lnk_g, const float* __restrict__ lnk_b,
    const float* __restrict__ ln2_g, const float* __restrict__ ln2_b,
    const float* __restrict__ fb1, const float* __restrict__ fb2,
    float* __restrict__ out_x, float* __restrict__ out_z)
{
  extern __shared__ Smem S[];
  Smem* s = S;
  int tid = threadIdx.x, lane = tid & 31, warp = tid >> 5;
  int t0 = blockIdx.x * TB;
  int b  = t0 >> 10;

  if (tid < KHc){
    s->mlp1[tid][0] = kW1[tid];
    s->mlp1[tid][1] = kW1[KHc+tid];
    s->mlp1[tid][2] = kb1[tid];
    s->mlp1[tid][3] = 0.f;
  }
  { int jj = tid >> 3, hx = tid & 7; s->kw2s[jj][hx] = kW2[jj*HH + hx]; }
  __syncthreads();

  float mn0=g_min[0], mx0=g_max[0], mn1=g_min[1], mx1=g_max[1];
  float st0 = __fdiv_rn(mx0-mn0, (float)(G1-1));
  float st1 = __fdiv_rn(mx1-mn1, (float)(G2-1));

  // ============ token phase: warp owns token t0+warp ============
  {
    int tg = t0 + warp;
    int cell = tg & (MM-1);
    int c1 = cell >> 5, c2 = cell & 31;
    float xg0 = (c1==G1-1) ? mx0 : (mn0 + (float)c1*st0);
    float xg1 = (c2==G2-1) ? mx1 : (mn1 + (float)c2*st1);
    int cnt = g_count[tg]; if (cnt > PP) cnt = PP;
    bool act = lane < cnt;

    int nid = 0; float2 xv = make_float2(0.f, 0.f);
    float2 stats = make_float2(0.f, 1.f);
    if (act){
      nid = g_ptid[tg*PP + lane];
      xv = ((const float2*)x)[(size_t)b*NN + nid];
      stats = g_stats[b*NN + nid];
    }

    // ---- pass 1: per-key logits in registers ----
    float pl[HH];
    if (act){
      const float4* pv = (const float4*)(g_plog + (size_t)(b*NN+nid)*HH);
      float4 pa = pv[0], pb = pv[1];
      pl[0]=pa.x; pl[1]=pa.y; pl[2]=pa.z; pl[3]=pa.w;
      pl[4]=pb.x; pl[5]=pb.y; pl[6]=pb.z; pl[7]=pb.w;
      float dx0 = xv.x - xg0, dx1 = xv.y - xg1;
      #pragma unroll 8
      for (int jj=0;jj<KHc;jj++){
        float4 m1 = *(const float4*)s->mlp1[jj];
        float hv = fmaxf(fmaf(dx0, m1.x, fmaf(dx1, m1.y, m1.z)), 0.f);
        float4 w2a = *(const float4*)&s->kw2s[jj][0];
        float4 w2b = *(const float4*)&s->kw2s[jj][4];
        pl[0]=fmaf(hv,w2a.x,pl[0]); pl[1]=fmaf(hv,w2a.y,pl[1]);
        pl[2]=fmaf(hv,w2a.z,pl[2]); pl[3]=fmaf(hv,w2a.w,pl[3]);
        pl[4]=fmaf(hv,w2b.x,pl[4]); pl[5]=fmaf(hv,w2b.y,pl[5]);
        pl[6]=fmaf(hv,w2b.z,pl[6]); pl[7]=fmaf(hv,w2b.w,pl[7]);
      }
    } else {
      #pragma unroll
      for (int h=0;h<HH;h++) pl[h] = -1e30f;
    }

    // ---- softmax ----
    int hh = lane >> 2;
    float d0h = g_dots0[hh];
    float m = reduce8_max(pl, lane);
    m = fmaxf(m, d0h);
    if ((lane & 3) == 0) s->p[warp][PP+1][hh] = m;
    __syncwarp();
    float4 ma4 = *(const float4*)&s->p[warp][PP+1][0];
    float4 mb4 = *(const float4*)&s->p[warp][PP+1][4];
    float mm[HH] = {ma4.x,ma4.y,ma4.z,ma4.w,mb4.x,mb4.y,mb4.z,mb4.w};
    float e[HH];
    #pragma unroll
    for (int h=0;h<HH;h++) e[h] = __expf(pl[h]-mm[h]);
    float ssum = reduce8(e, lane);
    float e0 = __expf(d0h - m);
    float inv = 1.f/(ssum + e0);
    __syncwarp();
    if ((lane & 3) == 0){
      s->p[warp][PP+1][hh] = inv;
      s->p[warp][0][hh] = e0*inv;
    }
    __syncwarp();
    float4 ia4 = *(const float4*)&s->p[warp][PP+1][0];
    float4 ib4 = *(const float4*)&s->p[warp][PP+1][4];
    float ii[HH] = {ia4.x,ia4.y,ia4.z,ia4.w,ib4.x,ib4.y,ib4.z,ib4.w};
    float p8[HH];
    #pragma unroll
    for (int h=0;h<HH;h++) p8[h] = e[h]*ii[h];
    if (act){
      float4* prow = (float4*)s->p[warp][lane+1];
      prow[0] = make_float4(p8[0],p8[1],p8[2],p8[3]);
      prow[1] = make_float4(p8[4],p8[5],p8[6],p8[7]);
    }
    __syncwarp();

    // ---- TE x-update ----
    {
      float ma = 0.125f*(p8[0]+p8[1]+p8[2]+p8[3]+p8[4]+p8[5]+p8[6]+p8[7]);
      float c0 = ma*xv.x, c1v = ma*xv.y;
      if (lane == 0){
        float4 pa = *(const float4*)&s->p[warp][0][0];
        float4 pb = *(const float4*)&s->p[warp][0][4];
        float ma0 = 0.125f*(pa.x+pa.y+pa.z+pa.w+pb.x+pb.y+pb.z+pb.w);
        c0 += ma0*xg0; c1v += ma0*xg1;
      }
      #pragma unroll
      for (int o=16;o;o>>=1){
        c0  += __shfl_xor_sync(0xffffffffu, c0, o);
        c1v += __shfl_xor_sync(0xffffffffu, c1v, o);
      }
      if (lane == 0){
        out_x[(size_t)tg*2]   = c0;
        out_x[(size_t)tg*2+1] = c1v;
      }
    }

    // ---- pass 2: zbar in two half-passes (heads 0-3, then 4-7) ----
    float4 lg = ((const float4*)lnk_g)[lane];
    float4 lb = ((const float4*)lnk_b)[lane];
    float4 lnkv = ((const float4*)g_lnk)[lane];
    #pragma unroll
    for (int half=0; half<2; half++){
      int hb = half*4;
      float4 p0h = *(const float4*)&s->p[warp][0][hb];
      float4 acc[4];
      acc[0]=make_float4(p0h.x*lnkv.x,p0h.x*lnkv.y,p0h.x*lnkv.z,p0h.x*lnkv.w);
      acc[1]=make_float4(p0h.y*lnkv.x,p0h.y*lnkv.y,p0h.y*lnkv.z,p0h.y*lnkv.w);
      acc[2]=make_float4(p0h.z*lnkv.x,p0h.z*lnkv.y,p0h.z*lnkv.z,p0h.z*lnkv.w);
      acc[3]=make_float4(p0h.w*lnkv.x,p0h.w*lnkv.y,p0h.w*lnkv.z,p0h.w*lnkv.w);
      float4 vbuf0, vbuf1;
      if (cnt > 0){
        int n = __shfl_sync(0xffffffffu, nid, 0);
        vbuf0 = ((const float4*)z)[(size_t)(b*NN+n)*32 + lane];
      }
      for (int k=0;k<cnt;k++){
        if (k+1 < cnt){
          int n = __shfl_sync(0xffffffffu, nid, k+1);
          vbuf1 = ((const float4*)z)[(size_t)(b*NN+n)*32 + lane];
        }
        float4 v = vbuf0;
        float mu = __shfl_sync(0xffffffffu, stats.x, k);
        float rs = __shfl_sync(0xffffffffu, stats.y, k);
        float z0=(v.x-mu)*rs*lg.x+lb.x, z1=(v.y-mu)*rs*lg.y+lb.y;
        float z2=(v.z-mu)*rs*lg.z+lb.z, z3=(v.w-mu)*rs*lg.w+lb.w;
        float4 pa = *(const float4*)&s->p[warp][k+1][hb];
        float pk[4] = {pa.x, pa.y, pa.z, pa.w};
        #pragma unroll
        for (int h=0;h<4;h++){
          acc[h].x = fmaf(pk[h], z0, acc[h].x);
          acc[h].y = fmaf(pk[h], z1, acc[h].y);
          acc[h].z = fmaf(pk[h], z2, acc[h].z);
          acc[h].w = fmaf(pk[h], z3, acc[h].w);
        }
        vbuf0 = vbuf1;
      }
      #pragma unroll
      for (int h=0;h<4;h++)
        ((float4*)s->zbar[warp][hb+h])[lane] = acc[h];
    }
  }
  __syncthreads();

  // ============ weight passes (R11 form) ============
  int f = tid & 127;
  int g = tid >> 7;
  int h = f >> 4;
  int tb0 = g*4;

  // aliases into pbuf (p is dead after token phase): 2048 floats <= 2176
  float* ln2b = &s->p[0][0][0];
  float* h1b  = ln2b + TB*EE;

  // ---- W1: out = zbar . Wv ----
  {
    WPASS_PROLOG(g_pWv)
    WPASS_LOOP(s->zbar[tb0+i][h])
    #pragma unroll
    for (int i=0;i<4;i++) s->out[tb0+i][f] = unpack_sum(accA[i]) + unpack_sum(accB[i]);
  }
  __syncthreads();

  // ---- W2: znew = latent + out @ Wo + bo ----
  {
    WPASS_PROLOG(g_pWo)
    WPASS_LOOP(s->out[tb0+i])
    float base = latent[f] + bo[f];
    #pragma unroll
    for (int i=0;i<4;i++) s->znew[tb0+i][f] = base + unpack_sum(accA[i]) + unpack_sum(accB[i]);
  }
  __syncthreads();

  // ---- LN2: warp per token ----
  {
    float4 g2 = ((const float4*)ln2_g)[lane];
    float4 b2 = ((const float4*)ln2_b)[lane];
    int t = warp;
    float4 v = ((const float4*)s->znew[t])[lane];
    float sv = v.x+v.y+v.z+v.w;
    #pragma unroll
    for (int o=16;o;o>>=1) sv += __shfl_xor_sync(0xffffffffu, sv, o);
    float mu = sv*(1.f/EE);
    float d0=v.x-mu, d1=v.y-mu, d2=v.z-mu, d3=v.w-mu;
    float q = d0*d0+d1*d1+d2*d2+d3*d3;
    #pragma unroll
    for (int o=16;o;o>>=1) q += __shfl_xor_sync(0xffffffffu, q, o);
    float rs = rsqrtf(q*(1.f/EE)+1e-5f);
    ((float4*)(ln2b + t*EE))[lane] = make_float4(d0*rs*g2.x+b2.x, d1*rs*g2.y+b2.y,
                                                 d2*rs*g2.z+b2.z, d3*rs*g2.w+b2.w);
  }
  __syncthreads();

  // ---- FFN1 ----
  {
    WPASS_PROLOG(g_pW1)
    WPASS_LOOP((ln2b + (tb0+i)*EE))
    float bias = fb1[f];
    #pragma unroll
    for (int i=0;i<4;i++)
      h1b[(tb0+i)*EE + f] = fmaxf(unpack_sum(accA[i]) + unpack_sum(accB[i]) + bias, 0.f);
  }
  __syncthreads();

  // ---- FFN2 + residual ----
  {
    WPASS_PROLOG(g_pW2)
    WPASS_LOOP((h1b + (tb0+i)*EE))
    float bias = fb2[f];
    #pragma unroll
    for (int i=0;i<4;i++)
      out_z[(size_t)(t0+tb0+i)*EE + f] = s->znew[tb0+i][f] + unpack_sum(accA[i]) + unpack_sum(accB[i]) + bias;
  }
}

// ---------------- launch ----------------
static cudaStream_t get_aux_stream(){
  static cudaStream_t s = [](){
    cudaStream_t st; cudaStreamCreateWithFlags(&st, cudaStreamNonBlocking); return st;
  }();
  return s;
}
static cudaEvent_t get_event(int which){
  static cudaEvent_t e0 = [](){
    cudaEvent_t e; cudaEventCreateWithFlags(&e, cudaEventDisableTiming); return e;
  }();
  static cudaEvent_t e1 = [](){
    cudaEvent_t e; cudaEventCreateWithFlags(&e, cudaEventDisableTiming); return e;
  }();
  return which ? e1 : e0;
}

extern "C" void kernel_launch(void* const* d_in, const int* in_sizes, int n_in,
                              void* d_out, int out_size){
  const float* x     = (const float*)d_in[0];
  const float* z     = (const float*)d_in[1];
  const float* latent= (const float*)d_in[6];
  const float* Wq    = (const float*)d_in[7];
  const float* Wk    = (const float*)d_in[8];
  const float* Wv    = (const float*)d_in[9];
  const float* Wo    = (const float*)d_in[10];
  const float* bo    = (const float*)d_in[11];
  const float* kW1   = (const float*)d_in[12];
  const float* kb1   = (const float*)d_in[13];
  const float* kW2   = (const float*)d_in[14];
  const float* kb2   = (const float*)d_in[15];
  const float* lnq_g = (const float*)d_in[16];
  const float* lnq_b = (const float*)d_in[17];
  const float* lnk_g = (const float*)d_in[18];
  const float* lnk_b = (const float*)d_in[19];
  const float* ln2_g = (const float*)d_in[20];
  const float* ln2_b = (const float*)d_in[21];
  const float* fW1   = (const float*)d_in[22];
  const float* fb1   = (const float*)d_in[23];
  const float* fW2   = (const float*)d_in[24];
  const float* fb2   = (const float*)d_in[25];

  float* out   = (float*)d_out;
  float* out_x = out;
  float* out_z = out + (size_t)TT*DXc;

  static_assert(sizeof(Smem) < 52*1024, "smem");
  cudaFuncSetAttribute(k_main, cudaFuncAttributeMaxDynamicSharedMemorySize, (int)sizeof(Smem));

  cudaStream_t aux = get_aux_stream();
  cudaEvent_t ev_fork = get_event(0), ev_join = get_event(1);

  cudaEventRecord(ev_fork, 0);
  cudaStreamWaitEvent(aux, ev_fork, 0);

  // default stream: k_pre -> k_minmax -> k_bin
  k_pre<<<32, 256>>>(Wv, Wo, fW1, fW2);
  k_minmax<<<128, 256>>>(x);
  k_bin<<<128, 256>>>(x);

  // aux stream: k_prep -> k_point
  k_prep<<<HH, 1024, 0, aux>>>(latent, Wq, Wk, lnq_g, lnq_b, lnk_g, lnk_b, kb1, kW2, kb2);
  k_point<<<BB*NN/32, 256, 0, aux>>>(z);

  cudaEventRecord(ev_join, aux);
  cudaStreamWaitEvent(0, ev_join, 0);

  k_main<<<TT/TB, 256, sizeof(Smem)>>>(x, z, latent, bo, kW1, kb1, kW2, kb2,
                                       lnk_g, lnk_b, ln2_g, ln2_b, fb1, fb2,
                                       out_x, out_z);
}